// round 4
// baseline (speedup 1.0000x reference)
#include <cuda_runtime.h>
#include <cstdint>
#include <cfloat>

#define NEG_SLOPE 0.01f

constexpr int Bv = 32, Pv = 512, Vv = 32, Fv = 16, Hv = 64;
constexpr int NG = Bv * Pv;          // 16384 (b,p) groups
constexpr int THREADS = 256;
constexpr int STRIDE = 68;           // padded row stride for activation buffers (conflict-free LDS.128)
constexpr int GRID = 296;            // 2 blocks per SM * 148 SMs

// Shared memory float layout:
//  W1s   [64*16]   = 1024
//  W2s   [64*128]  = 8192
//  W3s   [64*128]  = 8192
//  b1s,b2s,b3s     = 192
//  pl1, pl2        = 128
//  bufA  [32*68]   = 2176
//  bufB  [32*68]   = 2176
constexpr int SMEM_FLOATS = 1024 + 8192 + 8192 + 192 + 128 + 2176 + 2176; // 22080
constexpr int SMEM_BYTES  = SMEM_FLOATS * 4;                              // 88320

__global__ __launch_bounds__(THREADS, 2)
void fused_mlp_pool_kernel(const float* __restrict__ x,
                           const void*  __restrict__ maskp,
                           const float* __restrict__ W1,
                           const float* __restrict__ b1,
                           const float* __restrict__ W2,
                           const float* __restrict__ b2,
                           const float* __restrict__ W3,
                           const float* __restrict__ b3,
                           float* __restrict__ out)
{
    extern __shared__ float sm[];
    float* W1s = sm;                    // 1024
    float* W2s = sm + 1024;             // 8192
    float* W3s = sm + 1024 + 8192;      // 8192
    float* b1s = sm + 17408;
    float* b2s = b1s + 64;
    float* b3s = b2s + 64;
    float* pl1 = b3s + 64;              // 64
    float* pl2 = pl1 + 64;              // 64
    float* bufA = pl2 + 64;             // 32*68
    float* bufB = bufA + 32 * STRIDE;   // 32*68

    const int tid  = threadIdx.x;
    const int lane = tid & 31;          // = v
    const int warp = tid >> 5;          // 0..7
    const int hbase = warp * 8;

    // ---- stage weights into shared ----
    for (int i = tid; i < 1024; i += THREADS) W1s[i] = W1[i];
    for (int i = tid; i < 8192; i += THREADS) W2s[i] = W2[i];
    for (int i = tid; i < 8192; i += THREADS) W3s[i] = W3[i];
    if (tid < 64) { b1s[tid] = b1[tid]; b2s[tid] = b2[tid]; b3s[tid] = b3[tid]; }

    // ---- detect mask encoding (bool-u8 / int32 / float32) from byte pattern ----
    __shared__ int s_flags[4];
    if (tid < 4) s_flags[tid] = 0;
    __syncthreads();
    {
        int f0 = 0, f1 = 0, f23 = 0;
        const unsigned char* mb = (const unsigned char*)maskp;
        #pragma unroll
        for (int i = 0; i < 16; i++) {
            int idx = tid * 16 + i;      // scans first 4096 bytes (safe: >=512KB in any encoding)
            unsigned char c = mb[idx];
            if (c) { int m = idx & 3; if (m == 0) f0 = 1; else if (m == 1) f1 = 1; else f23 = 1; }
        }
        if (f0)  atomicOr(&s_flags[0], 1);
        if (f1)  atomicOr(&s_flags[1], 1);
        if (f23) atomicOr(&s_flags[2], 1);
    }
    __syncthreads();
    // u8 bool -> nonzero bytes at all offsets; int32 {0,1} -> only offset 0; float {0,1.0f} -> only offsets 2,3
    const int fmt = s_flags[1] ? 1 : (s_flags[0] ? 0 : (s_flags[2] ? 2 : 0));

    for (int g = blockIdx.x; g < NG; g += gridDim.x) {
        // ---- mask for this lane's v ----
        const int midx = g * Vv + lane;
        bool valid;
        if (fmt == 1)      valid = ((const unsigned char*)maskp)[midx] != 0;
        else if (fmt == 0) valid = ((const int*)maskp)[midx] != 0;
        else               valid = ((const float*)maskp)[midx] != 0.0f;
        const unsigned bal = __ballot_sync(0xffffffffu, valid);
        const bool anyv = (bal != 0);

        // ---- load this lane's x row (16 floats) ----
        const float4* xp = (const float4*)(x + ((size_t)g * Vv + lane) * Fv);
        float4 xr0 = xp[0], xr1 = xp[1], xr2 = xp[2], xr3 = xp[3];

        float acc[8];

        // ================= Layer 1: 16 -> 64 =================
        #pragma unroll
        for (int hh = 0; hh < 8; hh++) {
            const float4* w = (const float4*)(W1s + (hbase + hh) * 16);
            float s = b1s[hbase + hh];
            float4 w0 = w[0], w1 = w[1], w2 = w[2], w3 = w[3];
            s = fmaf(xr0.x, w0.x, s); s = fmaf(xr0.y, w0.y, s); s = fmaf(xr0.z, w0.z, s); s = fmaf(xr0.w, w0.w, s);
            s = fmaf(xr1.x, w1.x, s); s = fmaf(xr1.y, w1.y, s); s = fmaf(xr1.z, w1.z, s); s = fmaf(xr1.w, w1.w, s);
            s = fmaf(xr2.x, w2.x, s); s = fmaf(xr2.y, w2.y, s); s = fmaf(xr2.z, w2.z, s); s = fmaf(xr2.w, w2.w, s);
            s = fmaf(xr3.x, w3.x, s); s = fmaf(xr3.y, w3.y, s); s = fmaf(xr3.z, w3.z, s); s = fmaf(xr3.w, w3.w, s);
            acc[hh] = s;
        }
        {
            float outv[8], ng[8];
            #pragma unroll
            for (int hh = 0; hh < 8; hh++) {
                float r = acc[hh] > 0.0f ? acc[hh] : NEG_SLOPE * acc[hh];
                outv[hh] = valid ? r : 0.0f;
                ng[hh]   = valid ? r : -FLT_MAX;
            }
            #pragma unroll
            for (int off = 16; off >= 1; off >>= 1)
                #pragma unroll
                for (int hh = 0; hh < 8; hh++)
                    ng[hh] = fmaxf(ng[hh], __shfl_xor_sync(0xffffffffu, ng[hh], off));
            if (lane == 0) {
                #pragma unroll
                for (int hh = 0; hh < 8; hh++) pl1[hbase + hh] = anyv ? ng[hh] : 0.0f;
            }
            *(float4*)(bufA + lane * STRIDE + hbase)     = make_float4(outv[0], outv[1], outv[2], outv[3]);
            *(float4*)(bufA + lane * STRIDE + hbase + 4) = make_float4(outv[4], outv[5], outv[6], outv[7]);
        }
        __syncthreads();

        // ================= Layer 2: 128 -> 64 (pool half folded into per-group constant) =================
        {
            // c2[h] = b2[h] + sum_j pl1[j] * W2[h][64+j], computed cooperatively across the warp
            float2 pp = *(const float2*)(pl1 + 2 * lane);
            #pragma unroll
            for (int hh = 0; hh < 8; hh++) {
                float2 w2p = *(const float2*)(W2s + (hbase + hh) * 128 + 64 + 2 * lane);
                acc[hh] = pp.x * w2p.x + pp.y * w2p.y;
            }
            #pragma unroll
            for (int off = 16; off >= 1; off >>= 1)
                #pragma unroll
                for (int hh = 0; hh < 8; hh++)
                    acc[hh] += __shfl_xor_sync(0xffffffffu, acc[hh], off);
            #pragma unroll
            for (int hh = 0; hh < 8; hh++) acc[hh] += b2s[hbase + hh];
        }
        #pragma unroll
        for (int j = 0; j < 64; j += 4) {
            float4 a = *(const float4*)(bufA + lane * STRIDE + j);
            #pragma unroll
            for (int hh = 0; hh < 8; hh++) {
                float4 w = *(const float4*)(W2s + (hbase + hh) * 128 + j);
                acc[hh] = fmaf(a.x, w.x, fmaf(a.y, w.y, fmaf(a.z, w.z, fmaf(a.w, w.w, acc[hh]))));
            }
        }
        {
            float outv[8], ng[8];
            #pragma unroll
            for (int hh = 0; hh < 8; hh++) {
                float r = acc[hh] > 0.0f ? acc[hh] : NEG_SLOPE * acc[hh];
                outv[hh] = valid ? r : 0.0f;
                ng[hh]   = valid ? r : -FLT_MAX;
            }
            #pragma unroll
            for (int off = 16; off >= 1; off >>= 1)
                #pragma unroll
                for (int hh = 0; hh < 8; hh++)
                    ng[hh] = fmaxf(ng[hh], __shfl_xor_sync(0xffffffffu, ng[hh], off));
            if (lane == 0) {
                #pragma unroll
                for (int hh = 0; hh < 8; hh++) pl2[hbase + hh] = anyv ? ng[hh] : 0.0f;
            }
            *(float4*)(bufB + lane * STRIDE + hbase)     = make_float4(outv[0], outv[1], outv[2], outv[3]);
            *(float4*)(bufB + lane * STRIDE + hbase + 4) = make_float4(outv[4], outv[5], outv[6], outv[7]);
        }
        __syncthreads();

        // ================= Layer 3: 128 -> 64, only pool needed =================
        {
            float2 pp = *(const float2*)(pl2 + 2 * lane);
            #pragma unroll
            for (int hh = 0; hh < 8; hh++) {
                float2 w3p = *(const float2*)(W3s + (hbase + hh) * 128 + 64 + 2 * lane);
                acc[hh] = pp.x * w3p.x + pp.y * w3p.y;
            }
            #pragma unroll
            for (int off = 16; off >= 1; off >>= 1)
                #pragma unroll
                for (int hh = 0; hh < 8; hh++)
                    acc[hh] += __shfl_xor_sync(0xffffffffu, acc[hh], off);
            #pragma unroll
            for (int hh = 0; hh < 8; hh++) acc[hh] += b3s[hbase + hh];
        }
        #pragma unroll
        for (int j = 0; j < 64; j += 4) {
            float4 a = *(const float4*)(bufB + lane * STRIDE + j);
            #pragma unroll
            for (int hh = 0; hh < 8; hh++) {
                float4 w = *(const float4*)(W3s + (hbase + hh) * 128 + j);
                acc[hh] = fmaf(a.x, w.x, fmaf(a.y, w.y, fmaf(a.z, w.z, fmaf(a.w, w.w, acc[hh]))));
            }
        }
        {
            float ng[8];
            #pragma unroll
            for (int hh = 0; hh < 8; hh++) {
                float r = acc[hh] > 0.0f ? acc[hh] : NEG_SLOPE * acc[hh];
                ng[hh] = valid ? r : -FLT_MAX;
            }
            #pragma unroll
            for (int off = 16; off >= 1; off >>= 1)
                #pragma unroll
                for (int hh = 0; hh < 8; hh++)
                    ng[hh] = fmaxf(ng[hh], __shfl_xor_sync(0xffffffffu, ng[hh], off));
            if (lane == 0) {
                float4 r0 = make_float4(anyv ? ng[0] : 0.0f, anyv ? ng[1] : 0.0f,
                                        anyv ? ng[2] : 0.0f, anyv ? ng[3] : 0.0f);
                float4 r1 = make_float4(anyv ? ng[4] : 0.0f, anyv ? ng[5] : 0.0f,
                                        anyv ? ng[6] : 0.0f, anyv ? ng[7] : 0.0f);
                *(float4*)(out + (size_t)g * Hv + hbase)     = r0;
                *(float4*)(out + (size_t)g * Hv + hbase + 4) = r1;
            }
        }
        // no trailing sync needed: ping-pong buffers + the two intra-group barriers
        // make cross-iteration hazards impossible (bufA/pl1 writes are separated from
        // bufB/pl2 readers by the group's own barriers).
    }
}

extern "C" void kernel_launch(void* const* d_in, const int* in_sizes, int n_in,
                              void* d_out, int out_size)
{
    const float* x  = (const float*)d_in[0];
    const void*  mk = d_in[1];
    const float* W1 = (const float*)d_in[2];
    const float* b1 = (const float*)d_in[3];
    const float* W2 = (const float*)d_in[4];
    const float* b2 = (const float*)d_in[5];
    const float* W3 = (const float*)d_in[6];
    const float* b3 = (const float*)d_in[7];
    float* out = (float*)d_out;

    cudaFuncSetAttribute(fused_mlp_pool_kernel,
                         cudaFuncAttributeMaxDynamicSharedMemorySize, SMEM_BYTES);
    fused_mlp_pool_kernel<<<GRID, THREADS, SMEM_BYTES>>>(x, mk, W1, b1, W2, b2, W3, b3, out);
}

// round 10
// speedup vs baseline: 1.1668x; 1.1668x over previous
#include <cuda_runtime.h>
#include <cstdint>
#include <cfloat>

#define NEG_SLOPE 0.01f

constexpr int Vv = 32, Fv = 16, Hv = 64;
constexpr int NG = 32 * 512;         // 16384 groups
constexpr int GPP = 4;               // groups per pass (weight-load amortization factor)
constexpr int NPASS = NG / GPP;      // 4096
constexpr int THREADS = 256;
constexpr int STRIDE = 68;           // padded activation row stride (conflict-free LDS.128)
constexpr int GRID = 148;

// Shared float layout:
//  W1s [1024] | W2s [8192] | W3s [8192] | b1s,b2s,b3s [192] | pl1 [256] | pl2 [256]
//  bufA [4*32*68 = 8704] | bufB [8704]   => total 35520 floats = 142080 B
constexpr int OFF_W1 = 0;
constexpr int OFF_W2 = 1024;
constexpr int OFF_W3 = 9216;
constexpr int OFF_B1 = 17408;
constexpr int OFF_B2 = 17472;
constexpr int OFF_B3 = 17536;
constexpr int OFF_PL1 = 17600;
constexpr int OFF_PL2 = 17856;
constexpr int OFF_BUFA = 18112;
constexpr int OFF_BUFB = 26816;
constexpr int SMEM_FLOATS = 35520;
constexpr int SMEM_BYTES = SMEM_FLOATS * 4;

__device__ __forceinline__ float warp_max_f32(float v) {
    #pragma unroll
    for (int o = 16; o >= 1; o >>= 1)
        v = fmaxf(v, __shfl_xor_sync(0xffffffffu, v, o));
    return v;
}

__device__ __forceinline__ float warp_sum_f32(float v) {
    #pragma unroll
    for (int o = 16; o >= 1; o >>= 1)
        v += __shfl_xor_sync(0xffffffffu, v, o);
    return v;
}

__global__ __launch_bounds__(THREADS, 1)
void fused_mlp_pool_kernel(const float* __restrict__ x,
                           const void*  __restrict__ maskp,
                           const float* __restrict__ W1,
                           const float* __restrict__ b1,
                           const float* __restrict__ W2,
                           const float* __restrict__ b2,
                           const float* __restrict__ W3,
                           const float* __restrict__ b3,
                           float* __restrict__ out)
{
    extern __shared__ float sm[];
    float* W1s = sm + OFF_W1;
    float* W2s = sm + OFF_W2;
    float* W3s = sm + OFF_W3;
    float* b1s = sm + OFF_B1;
    float* b2s = sm + OFF_B2;
    float* b3s = sm + OFF_B3;
    float* pl1 = sm + OFF_PL1;      // [GPP][64]
    float* pl2 = sm + OFF_PL2;      // [GPP][64]
    float* bufA = sm + OFF_BUFA;    // [GPP][32][STRIDE]
    float* bufB = sm + OFF_BUFB;

    const int tid  = threadIdx.x;
    const int lane = tid & 31;      // = v
    const int warp = tid >> 5;      // 0..7
    const int hbase = warp * 8;

    // ---- stage weights into shared ----
    for (int i = tid; i < 1024; i += THREADS) W1s[i] = W1[i];
    for (int i = tid; i < 8192; i += THREADS) W2s[i] = W2[i];
    for (int i = tid; i < 8192; i += THREADS) W3s[i] = W3[i];
    if (tid < 64) { b1s[tid] = b1[tid]; b2s[tid] = b2[tid]; b3s[tid] = b3[tid]; }

    // ---- detect mask encoding (bool-u8 / int32 / float32) ----
    __shared__ int s_flags[4];
    if (tid < 4) s_flags[tid] = 0;
    __syncthreads();
    {
        int f0 = 0, f1 = 0, f23 = 0;
        const unsigned char* mb = (const unsigned char*)maskp;
        #pragma unroll
        for (int i = 0; i < 16; i++) {
            int idx = tid * 16 + i;
            unsigned char c = mb[idx];
            if (c) { int m = idx & 3; if (m == 0) f0 = 1; else if (m == 1) f1 = 1; else f23 = 1; }
        }
        if (f0)  atomicOr(&s_flags[0], 1);
        if (f1)  atomicOr(&s_flags[1], 1);
        if (f23) atomicOr(&s_flags[2], 1);
    }
    __syncthreads();
    const int fmt = s_flags[1] ? 1 : (s_flags[0] ? 0 : (s_flags[2] ? 2 : 0));

    for (int pass = blockIdx.x; pass < NPASS; pass += gridDim.x) {
        const int g0 = pass * GPP;

        // ---- masks (per group) ----
        bool valid[GPP], anyv[GPP];
        #pragma unroll
        for (int gi = 0; gi < GPP; gi++) {
            const int midx = (g0 + gi) * Vv + lane;
            bool v;
            if (fmt == 1)      v = ((const unsigned char*)maskp)[midx] != 0;
            else if (fmt == 0) v = ((const int*)maskp)[midx] != 0;
            else               v = ((const float*)maskp)[midx] != 0.0f;
            valid[gi] = v;
            anyv[gi]  = __ballot_sync(0xffffffffu, v) != 0;
        }

        // ---- x rows for all 4 groups ----
        float4 xr[GPP][4];
        #pragma unroll
        for (int gi = 0; gi < GPP; gi++) {
            const float4* xp = (const float4*)(x + ((size_t)(g0 + gi) * Vv + lane) * Fv);
            xr[gi][0] = xp[0]; xr[gi][1] = xp[1]; xr[gi][2] = xp[2]; xr[gi][3] = xp[3];
        }

        float acc[GPP][8];

        // ================= Layer 1: 16 -> 64 (weights loaded once, used 4x) =================
        #pragma unroll 2
        for (int hh = 0; hh < 8; hh++) {
            const float4* w = (const float4*)(W1s + (hbase + hh) * 16);
            float4 w0 = w[0], w1 = w[1], w2 = w[2], w3 = w[3];
            const float bb = b1s[hbase + hh];
            #pragma unroll
            for (int gi = 0; gi < GPP; gi++) {
                float s = bb;
                s = fmaf(xr[gi][0].x, w0.x, s); s = fmaf(xr[gi][0].y, w0.y, s);
                s = fmaf(xr[gi][0].z, w0.z, s); s = fmaf(xr[gi][0].w, w0.w, s);
                s = fmaf(xr[gi][1].x, w1.x, s); s = fmaf(xr[gi][1].y, w1.y, s);
                s = fmaf(xr[gi][1].z, w1.z, s); s = fmaf(xr[gi][1].w, w1.w, s);
                s = fmaf(xr[gi][2].x, w2.x, s); s = fmaf(xr[gi][2].y, w2.y, s);
                s = fmaf(xr[gi][2].z, w2.z, s); s = fmaf(xr[gi][2].w, w2.w, s);
                s = fmaf(xr[gi][3].x, w3.x, s); s = fmaf(xr[gi][3].y, w3.y, s);
                s = fmaf(xr[gi][3].z, w3.z, s); s = fmaf(xr[gi][3].w, w3.w, s);
                acc[gi][hh] = s;
            }
        }
        // epilogue L1 -> bufA, pl1
        #pragma unroll
        for (int gi = 0; gi < GPP; gi++) {
            float o[8], m[8];
            #pragma unroll
            for (int hh = 0; hh < 8; hh++) {
                float r = acc[gi][hh] > 0.0f ? acc[gi][hh] : NEG_SLOPE * acc[gi][hh];
                o[hh] = valid[gi] ? r : 0.0f;
                m[hh] = warp_max_f32(valid[gi] ? r : -FLT_MAX);
            }
            float* row = bufA + gi * (Vv * STRIDE) + lane * STRIDE + hbase;
            *(float4*)(row)     = make_float4(o[0], o[1], o[2], o[3]);
            *(float4*)(row + 4) = make_float4(o[4], o[5], o[6], o[7]);
            if (lane == 0) {
                float* pp = pl1 + gi * 64 + hbase;
                *(float4*)(pp)     = make_float4(anyv[gi] ? m[0] : 0.0f, anyv[gi] ? m[1] : 0.0f,
                                                 anyv[gi] ? m[2] : 0.0f, anyv[gi] ? m[3] : 0.0f);
                *(float4*)(pp + 4) = make_float4(anyv[gi] ? m[4] : 0.0f, anyv[gi] ? m[5] : 0.0f,
                                                 anyv[gi] ? m[6] : 0.0f, anyv[gi] ? m[7] : 0.0f);
            }
        }
        __syncthreads();

        // ================= Layer 2: 128 -> 64 =================
        {   // pool-side constant: acc[gi][hh] = b2[h] + sum_j pl1[gi][j] * W2[h][64+j]
            float2 wp[8];
            #pragma unroll
            for (int hh = 0; hh < 8; hh++)
                wp[hh] = *(const float2*)(W2s + (hbase + hh) * 128 + 64 + 2 * lane);
            float bb[8];
            #pragma unroll
            for (int hh = 0; hh < 8; hh++) bb[hh] = b2s[hbase + hh];
            #pragma unroll
            for (int gi = 0; gi < GPP; gi++) {
                float2 pp = *(const float2*)(pl1 + gi * 64 + 2 * lane);
                #pragma unroll
                for (int hh = 0; hh < 8; hh++)
                    acc[gi][hh] = warp_sum_f32(pp.x * wp[hh].x + pp.y * wp[hh].y) + bb[hh];
            }
        }
        #pragma unroll 2
        for (int j = 0; j < 64; j += 4) {
            float4 w[8];
            #pragma unroll
            for (int hh = 0; hh < 8; hh++)
                w[hh] = *(const float4*)(W2s + (hbase + hh) * 128 + j);
            float4 a[GPP];
            #pragma unroll
            for (int gi = 0; gi < GPP; gi++)
                a[gi] = *(const float4*)(bufA + gi * (Vv * STRIDE) + lane * STRIDE + j);
            #pragma unroll
            for (int gi = 0; gi < GPP; gi++)
                #pragma unroll
                for (int hh = 0; hh < 8; hh++)
                    acc[gi][hh] = fmaf(a[gi].x, w[hh].x, fmaf(a[gi].y, w[hh].y,
                                  fmaf(a[gi].z, w[hh].z, fmaf(a[gi].w, w[hh].w, acc[gi][hh]))));
        }
        // epilogue L2 -> bufB, pl2
        #pragma unroll
        for (int gi = 0; gi < GPP; gi++) {
            float o[8], m[8];
            #pragma unroll
            for (int hh = 0; hh < 8; hh++) {
                float r = acc[gi][hh] > 0.0f ? acc[gi][hh] : NEG_SLOPE * acc[gi][hh];
                o[hh] = valid[gi] ? r : 0.0f;
                m[hh] = warp_max_f32(valid[gi] ? r : -FLT_MAX);
            }
            float* row = bufB + gi * (Vv * STRIDE) + lane * STRIDE + hbase;
            *(float4*)(row)     = make_float4(o[0], o[1], o[2], o[3]);
            *(float4*)(row + 4) = make_float4(o[4], o[5], o[6], o[7]);
            if (lane == 0) {
                float* pp = pl2 + gi * 64 + hbase;
                *(float4*)(pp)     = make_float4(anyv[gi] ? m[0] : 0.0f, anyv[gi] ? m[1] : 0.0f,
                                                 anyv[gi] ? m[2] : 0.0f, anyv[gi] ? m[3] : 0.0f);
                *(float4*)(pp + 4) = make_float4(anyv[gi] ? m[4] : 0.0f, anyv[gi] ? m[5] : 0.0f,
                                                 anyv[gi] ? m[6] : 0.0f, anyv[gi] ? m[7] : 0.0f);
            }
        }
        __syncthreads();

        // ================= Layer 3: 128 -> 64 (pool only) =================
        {
            float2 wp[8];
            #pragma unroll
            for (int hh = 0; hh < 8; hh++)
                wp[hh] = *(const float2*)(W3s + (hbase + hh) * 128 + 64 + 2 * lane);
            float bb[8];
            #pragma unroll
            for (int hh = 0; hh < 8; hh++) bb[hh] = b3s[hbase + hh];
            #pragma unroll
            for (int gi = 0; gi < GPP; gi++) {
                float2 pp = *(const float2*)(pl2 + gi * 64 + 2 * lane);
                #pragma unroll
                for (int hh = 0; hh < 8; hh++)
                    acc[gi][hh] = warp_sum_f32(pp.x * wp[hh].x + pp.y * wp[hh].y) + bb[hh];
            }
        }
        #pragma unroll 2
        for (int j = 0; j < 64; j += 4) {
            float4 w[8];
            #pragma unroll
            for (int hh = 0; hh < 8; hh++)
                w[hh] = *(const float4*)(W3s + (hbase + hh) * 128 + j);
            float4 a[GPP];
            #pragma unroll
            for (int gi = 0; gi < GPP; gi++)
                a[gi] = *(const float4*)(bufB + gi * (Vv * STRIDE) + lane * STRIDE + j);
            #pragma unroll
            for (int gi = 0; gi < GPP; gi++)
                #pragma unroll
                for (int hh = 0; hh < 8; hh++)
                    acc[gi][hh] = fmaf(a[gi].x, w[hh].x, fmaf(a[gi].y, w[hh].y,
                                  fmaf(a[gi].z, w[hh].z, fmaf(a[gi].w, w[hh].w, acc[gi][hh]))));
        }
        // final epilogue: pool3 -> out
        #pragma unroll
        for (int gi = 0; gi < GPP; gi++) {
            float m[8];
            #pragma unroll
            for (int hh = 0; hh < 8; hh++) {
                float r = acc[gi][hh] > 0.0f ? acc[gi][hh] : NEG_SLOPE * acc[gi][hh];
                m[hh] = warp_max_f32(valid[gi] ? r : -FLT_MAX);
            }
            if (lane == 0) {
                float* op = out + (size_t)(g0 + gi) * Hv + hbase;
                *(float4*)(op)     = make_float4(anyv[gi] ? m[0] : 0.0f, anyv[gi] ? m[1] : 0.0f,
                                                 anyv[gi] ? m[2] : 0.0f, anyv[gi] ? m[3] : 0.0f);
                *(float4*)(op + 4) = make_float4(anyv[gi] ? m[4] : 0.0f, anyv[gi] ? m[5] : 0.0f,
                                                 anyv[gi] ? m[6] : 0.0f, anyv[gi] ? m[7] : 0.0f);
            }
        }
        // cross-pass hazards covered by the two intra-pass barriers:
        // bufA/pl1 writes vs readers separated by sync1; bufB/pl2 writes vs
        // readers separated by sync2 of this pass + sync1 of the next.
    }
}

extern "C" void kernel_launch(void* const* d_in, const int* in_sizes, int n_in,
                              void* d_out, int out_size)
{
    const float* x  = (const float*)d_in[0];
    const void*  mk = d_in[1];
    const float* W1 = (const float*)d_in[2];
    const float* b1 = (const float*)d_in[3];
    const float* W2 = (const float*)d_in[4];
    const float* b2 = (const float*)d_in[5];
    const float* W3 = (const float*)d_in[6];
    const float* b3 = (const float*)d_in[7];
    float* out = (float*)d_out;

    cudaFuncSetAttribute(fused_mlp_pool_kernel,
                         cudaFuncAttributeMaxDynamicSharedMemorySize, SMEM_BYTES);
    fused_mlp_pool_kernel<<<GRID, THREADS, SMEM_BYTES>>>(x, mk, W1, b1, W2, b2, W3, b3, out);
}